// round 10
// baseline (speedup 1.0000x reference)
#include <cuda_runtime.h>
#include <math.h>

// ----------------------------------------------------------------------------
// Strict2_5DLoss — single persistent kernel, v5: one WARP per task, all
// static. 592 blocks x 8 warps = 4736 consumers >= 3456 tasks, so every task
// starts immediately: no queue, no per-task block barriers.
//   pair tasks   (768): blocks 0..255, warps 0..2  -> t = bid*3 + wid
//   dense chunks (2688 x 256 cells): all remaining warps, statically indexed
// Pair task (warp-local): bbox scan on squared segment distances (sqrt only
// after d^2 prefilter -> reference-exact keys), candidates packed as
// (dist_bits<<32)|idx u64 in a per-warp smem buffer, two-level 256-bin
// histogram select of the 64 smallest (u64 order == reference stable top-k
// order), direct reg/cls/pos accumulation; objectness via per-unique-cell
// correction with an atomicOr dedup bitmask. Dense chunk: product-batched
// softplus over 256 cells. Grid barrier; block 0 finalizes; others clear the
// bitmask; exit counter resets barrier state for graph-replay determinism.
// ----------------------------------------------------------------------------

#define NT    256
#define GRID  592
#define CAP   1280
#define NPAIR 768
#define TOTAL_CELLS 688128
#define NBITS (TOTAL_CELLS / 32)
#define NDCH  2688                   // 2688 * 256 = 688128

__device__ int g_arrive = 0, g_exit = 0;
__device__ unsigned g_bits[NBITS];   // zero-init; cleared every run
__device__ double g_part[GRID][5];   // reg, cls, obj, pos, posnow

__device__ __forceinline__ float fast_sp(float x) {   // softplus via MUFU
    return fmaxf(x, 0.0f) + __logf(1.0f + __expf(-fabsf(x)));
}

// Warp-local: given a 256-bin histogram, find bin containing 0-based rank T
// and count of keys strictly below that bin. Full-warp collective.
__device__ __forceinline__ void pivot_warp(const int* hist, int T,
                                           int lane, int& bin, int& below) {
    int base = lane * 8, s = 0;
#pragma unroll
    for (int i = 0; i < 8; i++) s += hist[base + i];
    int pre = s;
#pragma unroll
    for (int o = 1; o < 32; o <<= 1) {
        int v = __shfl_up_sync(0xffffffffu, pre, o);
        if (lane >= o) pre += v;
    }
    int excl = pre - s;
    bool has = (excl <= T) && (T < pre);
    unsigned mk = __ballot_sync(0xffffffffu, has);
    int pl = __ffs((int)mk) - 1;
    int b = 0, c = 0;
    if (lane == pl) {
        c = excl; b = base;
        while (c + hist[b] <= T) { c += hist[b]; b++; }
    }
    bin   = __shfl_sync(0xffffffffu, b, pl);
    below = __shfl_sync(0xffffffffu, c, pl);
}

__global__ void __launch_bounds__(NT, 4)
fused_kernel(const float* __restrict__ reg0, const float* __restrict__ obj0,
             const float* __restrict__ cls0,
             const float* __restrict__ reg1, const float* __restrict__ obj1,
             const float* __restrict__ cls1,
             const float* __restrict__ reg2, const float* __restrict__ obj2,
             const float* __restrict__ cls2,
             const float* __restrict__ gt, float* __restrict__ out) {
    __shared__ unsigned long long s_key[3][CAP];   // pair warps only (wid<3)
    __shared__ int    s_hist[3][256];
    __shared__ int    s_cnt[3];
    __shared__ double s_w[8][5];

    const int tid  = threadIdx.x;
    const int bid  = blockIdx.x;
    const int wid  = tid >> 5;
    const int lane = tid & 31;

    double acc[5];  // 0:reg 1:cls 2:obj 3:pos 4:posnow
#pragma unroll
    for (int c = 0; c < 5; c++) acc[c] = 0.0;

    const bool isPair = (bid < 256) && (wid < 3);

    if (isPair) {
        // ================= pair task t = bid*3 + wid =================
        const int t   = bid * 3 + wid;
        const int lvl = t >> 8;
        const int p   = t & 255;
        const int b   = p >> 5;
        const int g   = p & 31;
        const int lg  = 8 - lvl;
        const int Ws  = 1 << lg;
        const int HW  = Ws * Ws;
        const float st = (float)(8 << lvl);

        const float* reg = (lvl == 0) ? reg0 : (lvl == 1) ? reg1 : reg2;
        const float* cls = (lvl == 0) ? cls0 : (lvl == 1) ? cls1 : cls2;
        const float* obj = (lvl == 0) ? obj0 : (lvl == 1) ? obj1 : obj2;
        const int markBase =
            ((lvl == 0) ? 0 : (lvl == 1) ? 524288 : 655360) + b * HW;

        // 6 gt floats: one 32B segment, broadcast via shfl
        const float* gp = gt + (size_t)(b * 32 + g) * 6;
        float gv = (lane < 6) ? gp[lane] : 0.0f;
        const float Ax = __shfl_sync(0xffffffffu, gv, 0);
        const float Ay = __shfl_sync(0xffffffffu, gv, 1);
        const float Bx = __shfl_sync(0xffffffffu, gv, 2);
        const float By = __shfl_sync(0xffffffffu, gv, 3);
        const float Cx = __shfl_sync(0xffffffffu, gv, 4);
        const float Cy = __shfl_sync(0xffffffffu, gv, 5);

        if (lane == 0) s_cnt[wid] = 0;

        float minx = fminf(Ax, fminf(Bx, Cx)) - 3.0f;
        float maxx = fmaxf(Ax, fmaxf(Bx, Cx)) + 3.0f;
        float miny = fminf(Ay, fminf(By, Cy)) - 3.0f;
        float maxy = fmaxf(Ay, fmaxf(By, Cy)) + 3.0f;
        int ix0 = max(0,      (int)floorf(minx / st - 0.5f));
        int ix1 = min(Ws - 1, (int)floorf(maxx / st - 0.5f) + 1);
        int iy0 = max(0,      (int)floorf(miny / st - 0.5f));
        int iy1 = min(Ws - 1, (int)floorf(maxy / st - 0.5f) + 1);
        int nx = ix1 - ix0 + 1; if (nx < 0) nx = 0;
        int ny = iy1 - iy0 + 1; if (ny < 0) ny = 0;
        const int tot = nx * ny;
        const float rnx = __fdividef(1.0f, (float)nx);

        const float e0x = Bx - Ax, e0y = By - Ay;
        const float e1x = Cx - Bx, e1y = Cy - By;
        const float e2x = Ax - Cx, e2y = Ay - Cy;
        const float i0 = __fdividef(1.0f, e0x * e0x + e0y * e0y + 1e-9f);
        const float i1 = __fdividef(1.0f, e1x * e1x + e1y * e1y + 1e-9f);
        const float i2 = __fdividef(1.0f, e2x * e2x + e2y * e2y + 1e-9f);

        __syncwarp();

        for (int c = lane; c < tot; c += 32) {
            int iy = (int)((float)c * rnx);
            int ix = c - iy * nx;
            if (ix < 0) { iy--; ix += nx; }
            else if (ix >= nx) { iy++; ix -= nx; }
            ix += ix0; iy += iy0;
            float px = (ix + 0.5f) * st;
            float py = (iy + 0.5f) * st;

            float d1 = (px - Bx) * (Ay - By) - (Ax - Bx) * (py - By);
            float d2 = (px - Cx) * (By - Cy) - (Bx - Cx) * (py - Cy);
            float d3 = (px - Ax) * (Cy - Ay) - (Cx - Ax) * (py - Ay);
            bool hneg = (d1 < 0.0f) || (d2 < 0.0f) || (d3 < 0.0f);
            bool hpos = (d1 > 0.0f) || (d2 > 0.0f) || (d3 > 0.0f);
            bool inside = !(hneg && hpos);

            float wx = px - Ax, wy = py - Ay;
            float tt = fminf(fmaxf((wx * e0x + wy * e0y) * i0, 0.0f), 1.0f);
            float dx = wx - tt * e0x, dy = wy - tt * e0y;
            float dd = dx * dx + dy * dy;
            wx = px - Bx; wy = py - By;
            tt = fminf(fmaxf((wx * e1x + wy * e1y) * i1, 0.0f), 1.0f);
            dx = wx - tt * e1x; dy = wy - tt * e1y;
            dd = fminf(dd, dx * dx + dy * dy);
            wx = px - Cx; wy = py - Cy;
            tt = fminf(fmaxf((wx * e2x + wy * e2y) * i2, 0.0f), 1.0f);
            dx = wx - tt * e2x; dy = wy - tt * e2y;
            dd = fminf(dd, dx * dx + dy * dy);

            if (inside || dd <= 9.00001f) {
                float dist = sqrtf(dd + 1e-12f);   // exact: matches reference
                if (inside || dist <= 3.0f) {
                    int slot = atomicAdd(&s_cnt[wid], 1);
                    if (slot < CAP)
                        s_key[wid][slot] =
                            ((unsigned long long)__float_as_uint(dist) << 32)
                            | (unsigned)(iy * Ws + ix);
                }
            }
        }
        __syncwarp();
        const int count = min(s_cnt[wid], CAP);
        const float inv = 1.0f / st;
        const unsigned long long* key = s_key[wid];
        int* hist = s_hist[wid];

        // ---- warp-local two-level histogram select of 64 smallest ----
        int pb = 256, sb = 256, r2 = 0;     // count<=64 -> select all
        if (count > 64) {
#pragma unroll
            for (int i = 0; i < 8; i++) hist[lane * 8 + i] = 0;
            __syncwarp();
            for (int e = lane; e < count; e += 32)
                atomicAdd(&hist[(int)((key[e] >> 55) & 0xFF)], 1);
            __syncwarp();
            int bb, cc;
            pivot_warp(hist, 63, lane, bb, cc);
            pb = bb;
            const int need = 64 - cc;       // 1..hist[pb]
            const int hpb  = hist[pb];
            __syncwarp();
            if (hpb > need) {
#pragma unroll
                for (int i = 0; i < 8; i++) hist[lane * 8 + i] = 0;
                __syncwarp();
                for (int e = lane; e < count; e += 32) {
                    unsigned long long k = key[e];
                    if ((int)((k >> 55) & 0xFF) == pb)
                        atomicAdd(&hist[(int)((k >> 47) & 0xFF)], 1);
                }
                __syncwarp();
                pivot_warp(hist, need - 1, lane, bb, cc);
                sb = bb;
                r2 = need - cc;             // 1..subhist[sb]
            }
        }

        float regA = 0.0f, clsA = 0.0f, objA = 0.0f;
        int nv = 0, nn = 0;

        for (int e = lane; e < count; e += 32) {
            const unsigned long long ke = key[e];
            const int eB = (int)((ke >> 55) & 0xFF);
            bool sel;
            if (eB != pb) sel = (eB < pb);
            else {
                const int mB = (int)((ke >> 47) & 0xFF);
                if (mB != sb) sel = (mB < sb);
                else {
                    const unsigned long long hi = ke >> 47;
                    int rank = 0;
                    for (int j = 0; j < count; j++) {
                        unsigned long long kj = key[j];
                        rank += (kj < ke) && ((kj >> 47) == hi);
                    }
                    sel = (rank < r2);
                }
            }
            if (sel) {
                const int ie = (int)(ke & 0xffffffffu);
                nv++;
                clsA += fast_sp(-cls[(size_t)b * HW + ie]);

                int ix = ie & (Ws - 1), iy = ie >> lg;
                float ax = (ix + 0.5f) * st;
                float ay = (iy + 0.5f) * st;
                float g0x = (Ax - ax) * inv, g0y = (Ay - ay) * inv;
                float g1x = (Bx - ax) * inv, g1y = (By - ay) * inv;
                float g2x = (Cx - ax) * inv, g2y = (Cy - ay) * inv;

                const float* rb = reg + (size_t)b * 6 * HW + ie;
                float p0x = fminf(fmaxf(rb[0],            -64.0f), 64.0f);
                float p0y = fminf(fmaxf(rb[(size_t)HW],   -64.0f), 64.0f);
                float p1x = fminf(fmaxf(rb[(size_t)2*HW], -64.0f), 64.0f);
                float p1y = fminf(fmaxf(rb[(size_t)3*HW], -64.0f), 64.0f);
                float p2x = fminf(fmaxf(rb[(size_t)4*HW], -64.0f), 64.0f);
                float p2y = fminf(fmaxf(rb[(size_t)5*HW], -64.0f), 64.0f);

                float p0 = (p0x - g0x) * (p0x - g0x)
                         + (p0y - g0y) * (p0y - g0y);
                float d11 = sqrtf((p1x-g1x)*(p1x-g1x) + (p1y-g1y)*(p1y-g1y));
                float d12 = sqrtf((p1x-g2x)*(p1x-g2x) + (p1y-g2y)*(p1y-g2y));
                float d21 = sqrtf((p2x-g1x)*(p2x-g1x) + (p2y-g1y)*(p2y-g1y));
                float d22 = sqrtf((p2x-g2x)*(p2x-g2x) + (p2y-g2y)*(p2y-g2y));
                float cd = fminf(d11, d12) + fminf(d21, d22)
                         + fminf(d11, d21) + fminf(d12, d22);
                regA += p0 + cd;

                int cell = markBase + ie;
                unsigned bit = 1u << (cell & 31);
                unsigned old = atomicOr(&g_bits[cell >> 5], bit);
                if (!(old & bit)) {
                    float x = obj[(size_t)b * HW + ie];
                    objA += 1.2f * fast_sp(-x) - fast_sp(x);
                    nn++;
                }
            }
        }
        acc[0] = (double)regA;
        acc[1] = (double)clsA;
        acc[2] = (double)objA;
        acc[3] = (double)nv;
        acc[4] = (double)nn;
    } else {
        // ================= dense objectness chunk (256 cells) =================
        int D = (bid < 256) ? (bid * 5 + (wid - 3))
                            : (1280 + (bid - 256) * 8 + wid);
        if (D < NDCH) {
            int base = D * 256;                 // chunk never crosses tensors
            const float* src; int off;
            if (base < 524288)      { src = obj0; off = base; }
            else if (base < 655360) { src = obj1; off = base - 524288; }
            else                    { src = obj2; off = base - 655360; }
            const float4* s4 = (const float4*)(src + off);
            float mx = 0.0f, prod = 1.0f;
#pragma unroll
            for (int k = 0; k < 2; k++) {
                float4 v = s4[lane + k * 32];
                mx += fmaxf(v.x, 0.0f) + fmaxf(v.y, 0.0f)
                    + fmaxf(v.z, 0.0f) + fmaxf(v.w, 0.0f);
                prod *= (1.0f + __expf(-fabsf(v.x)))
                      * (1.0f + __expf(-fabsf(v.y)))
                      * (1.0f + __expf(-fabsf(v.z)))
                      * (1.0f + __expf(-fabsf(v.w)));
            }
            acc[2] = (double)(mx + __logf(prod));
        }
    }

    // ================= block reduce -> per-block partials =================
#pragma unroll
    for (int c = 0; c < 5; c++) {
        double v = acc[c];
#pragma unroll
        for (int o = 16; o > 0; o >>= 1)
            v += __shfl_down_sync(0xffffffffu, v, o);
        if (lane == 0) s_w[wid][c] = v;
    }
    __syncthreads();
    if (wid == 0) {
#pragma unroll
        for (int c = 0; c < 5; c++) {
            double v = (lane < 8) ? s_w[lane][c] : 0.0;
#pragma unroll
            for (int o = 4; o > 0; o >>= 1)
                v += __shfl_down_sync(0xffffffffu, v, o);
            if (lane == 0) g_part[bid][c] = v;
        }
    }

    // ================= grid barrier =================
    if (tid == 0) {
        __threadfence();
        atomicAdd(&g_arrive, 1);
        while (*(volatile int*)&g_arrive < GRID) __nanosleep(32);
        __threadfence();
    }
    __syncthreads();

    // ================= finalize + cleanup =================
    if (bid == 0) {
        double v[5];
#pragma unroll
        for (int c = 0; c < 5; c++) v[c] = 0.0;
        for (int i = tid; i < GRID; i += NT)
#pragma unroll
            for (int c = 0; c < 5; c++) v[c] += g_part[i][c];
#pragma unroll
        for (int c = 0; c < 5; c++) {
            double r = v[c];
#pragma unroll
            for (int o = 16; o > 0; o >>= 1)
                r += __shfl_down_sync(0xffffffffu, r, o);
            if (lane == 0) s_w[wid][c] = r;
        }
        __syncthreads();
        if (tid == 0) {
            double tot[5];
#pragma unroll
            for (int c = 0; c < 5; c++) {
                double r = 0.0;
                for (int w = 0; w < 8; w++) r += s_w[w][c];
                tot[c] = r;
            }
            double pos_eps = fmax(tot[3], 1.0);
            double neg = fmax((double)TOTAL_CELLS - tot[4], 1.0);
            double total = tot[0] / pos_eps
                         + tot[2] / (pos_eps + neg)
                         + tot[1] / pos_eps;
            float tt = (float)total;
            out[0] = isfinite(tt) ? tt : 0.0f;
        }
    } else {
        for (int i = (bid - 1) * NT + tid; i < NBITS; i += (GRID - 1) * NT)
            g_bits[i] = 0u;
    }

    // ================= exit counter: reset barrier state =================
    __syncthreads();
    if (tid == 0) {
        __threadfence();
        int r = atomicAdd(&g_exit, 1);
        if (r == GRID - 1) { g_arrive = 0; g_exit = 0; }
    }
}

extern "C" void kernel_launch(void* const* d_in, const int* in_sizes, int n_in,
                              void* d_out, int out_size) {
    (void)in_sizes; (void)n_in; (void)out_size;
    fused_kernel<<<GRID, NT>>>(
        (const float*)d_in[0], (const float*)d_in[1], (const float*)d_in[2],
        (const float*)d_in[3], (const float*)d_in[4], (const float*)d_in[5],
        (const float*)d_in[6], (const float*)d_in[7], (const float*)d_in[8],
        (const float*)d_in[9], (float*)d_out);
}

// round 14
// speedup vs baseline: 1.6033x; 1.6033x over previous
#include <cuda_runtime.h>
#include <math.h>

// ----------------------------------------------------------------------------
// Strict2_5DLoss — single persistent kernel, v6.
// Static one-wave schedule (592 blocks = 4/SM x 148):
//   blocks   0..255 : 2 x 128-thread warpgroups -> lvl0 (t<256) + lvl1 tasks
//   blocks 256..591 : 8 warps; first 256 warp-slots run lvl2 tasks (+1 extra
//                     dense chunk each), the rest one 256-cell dense chunk.
// No grid barrier: each block atomicAdds 5 double partials; the LAST block to
// finish (done counter) finalizes, writes the scalar, resets totals, bumps
// the epoch. Dedup uses epoch-marked u32 cells (never cleared).
// Selection: two-level 256-bin histogram over (dist_bits<<32)|idx u64 keys ==
// reference's stable top-64 (sqrt computed only after d^2 prefilter).
// ----------------------------------------------------------------------------

#define NT    256
#define GRID  592
#define CAP0  2048                  // warpgroup tasks (lvl0/lvl1)
#define CAPW  256                   // warp tasks (lvl2)
#define TOTAL_CELLS 688128          // 8*(65536+16384+4096)

__device__ unsigned g_epoch = 0;    // current epoch = g_epoch + 1
__device__ unsigned g_done  = 0;
__device__ double   g_tot[5];       // reg, cls, obj, pos, posnow (reset by last block)
__device__ unsigned g_mark[TOTAL_CELLS];   // epoch marks; never cleared

__device__ __forceinline__ float fast_sp(float x) {   // softplus via MUFU
    return fmaxf(x, 0.0f) + __logf(1.0f + __expf(-fabsf(x)));
}

// One warp: find bin containing 0-based rank T in a 256-bin histogram, and
// the count of keys strictly below that bin.
__device__ __forceinline__ void pivot_warp(const int* hist, int T,
                                           int lane, int& bin, int& below) {
    int base = lane * 8, s = 0;
#pragma unroll
    for (int i = 0; i < 8; i++) s += hist[base + i];
    int pre = s;
#pragma unroll
    for (int o = 1; o < 32; o <<= 1) {
        int v = __shfl_up_sync(0xffffffffu, pre, o);
        if (lane >= o) pre += v;
    }
    int excl = pre - s;
    bool has = (excl <= T) && (T < pre);
    unsigned mk = __ballot_sync(0xffffffffu, has);
    int pl = __ffs((int)mk) - 1;
    int b = 0, c = 0;
    if (lane == pl) {
        c = excl; b = base;
        while (c + hist[b] <= T) { c += hist[b]; b++; }
    }
    bin   = __shfl_sync(0xffffffffu, b, pl);
    below = __shfl_sync(0xffffffffu, c, pl);
}

template<int GS>
__device__ __forceinline__ void gsync(int barid) {
    if (GS == 128) asm volatile("bar.sync %0, 128;" :: "r"(barid) : "memory");
    else __syncwarp();
}

struct SmemG { unsigned long long key[2][CAP0]; int hist[2][256]; int scr[2][4]; };
struct SmemW { unsigned long long key[8][CAPW]; int hist[8][256]; int scr[8][4]; };
union SmemU { SmemG g; SmemW w; };

template<int GS, int CAP>
__device__ void pair_task(int t, int gl, int barid,
                          unsigned long long* key, int* hist, int* scr,
                          const float* __restrict__ reg0, const float* __restrict__ obj0,
                          const float* __restrict__ cls0,
                          const float* __restrict__ reg1, const float* __restrict__ obj1,
                          const float* __restrict__ cls1,
                          const float* __restrict__ reg2, const float* __restrict__ obj2,
                          const float* __restrict__ cls2,
                          const float* __restrict__ gt, unsigned epoch, double* acc) {
    const int lane = gl & 31;
    const int lvl = t >> 8;
    const int p   = t & 255;
    const int b   = p >> 5;
    const int g   = p & 31;
    const int lg  = 8 - lvl;
    const int Ws  = 1 << lg;
    const int HW  = Ws * Ws;
    const float st = (float)(8 << lvl);

    const float* reg = (lvl == 0) ? reg0 : (lvl == 1) ? reg1 : reg2;
    const float* cls = (lvl == 0) ? cls0 : (lvl == 1) ? cls1 : cls2;
    const float* obj = (lvl == 0) ? obj0 : (lvl == 1) ? obj1 : obj2;
    const int markBase =
        ((lvl == 0) ? 0 : (lvl == 1) ? 524288 : 655360) + b * HW;

    // 6 gt floats: each warp loads + shfl-broadcasts
    const float* gp = gt + (size_t)(b * 32 + g) * 6;
    float gv = (lane < 6) ? gp[lane] : 0.0f;
    const float Ax = __shfl_sync(0xffffffffu, gv, 0);
    const float Ay = __shfl_sync(0xffffffffu, gv, 1);
    const float Bx = __shfl_sync(0xffffffffu, gv, 2);
    const float By = __shfl_sync(0xffffffffu, gv, 3);
    const float Cx = __shfl_sync(0xffffffffu, gv, 4);
    const float Cy = __shfl_sync(0xffffffffu, gv, 5);

    if (gl == 0) scr[0] = 0;

    float minx = fminf(Ax, fminf(Bx, Cx)) - 3.0f;
    float maxx = fmaxf(Ax, fmaxf(Bx, Cx)) + 3.0f;
    float miny = fminf(Ay, fminf(By, Cy)) - 3.0f;
    float maxy = fmaxf(Ay, fmaxf(By, Cy)) + 3.0f;
    int ix0 = max(0,      (int)floorf(minx / st - 0.5f));
    int ix1 = min(Ws - 1, (int)floorf(maxx / st - 0.5f) + 1);
    int iy0 = max(0,      (int)floorf(miny / st - 0.5f));
    int iy1 = min(Ws - 1, (int)floorf(maxy / st - 0.5f) + 1);
    int nx = ix1 - ix0 + 1; if (nx < 0) nx = 0;
    int ny = iy1 - iy0 + 1; if (ny < 0) ny = 0;
    const int tot = nx * ny;
    const float rnx = __fdividef(1.0f, (float)nx);

    const float e0x = Bx - Ax, e0y = By - Ay;
    const float e1x = Cx - Bx, e1y = Cy - By;
    const float e2x = Ax - Cx, e2y = Ay - Cy;
    const float i0 = __fdividef(1.0f, e0x * e0x + e0y * e0y + 1e-9f);
    const float i1 = __fdividef(1.0f, e1x * e1x + e1y * e1y + 1e-9f);
    const float i2 = __fdividef(1.0f, e2x * e2x + e2y * e2y + 1e-9f);

    gsync<GS>(barid);

    for (int c = gl; c < tot; c += GS) {
        int iy = (int)((float)c * rnx);
        int ix = c - iy * nx;
        if (ix < 0) { iy--; ix += nx; }
        else if (ix >= nx) { iy++; ix -= nx; }
        ix += ix0; iy += iy0;
        float px = (ix + 0.5f) * st;
        float py = (iy + 0.5f) * st;

        float d1 = (px - Bx) * (Ay - By) - (Ax - Bx) * (py - By);
        float d2 = (px - Cx) * (By - Cy) - (Bx - Cx) * (py - Cy);
        float d3 = (px - Ax) * (Cy - Ay) - (Cx - Ax) * (py - Ay);
        bool hneg = (d1 < 0.0f) || (d2 < 0.0f) || (d3 < 0.0f);
        bool hpos = (d1 > 0.0f) || (d2 > 0.0f) || (d3 > 0.0f);
        bool inside = !(hneg && hpos);

        float wx = px - Ax, wy = py - Ay;
        float tt = fminf(fmaxf((wx * e0x + wy * e0y) * i0, 0.0f), 1.0f);
        float dx = wx - tt * e0x, dy = wy - tt * e0y;
        float dd = dx * dx + dy * dy;
        wx = px - Bx; wy = py - By;
        tt = fminf(fmaxf((wx * e1x + wy * e1y) * i1, 0.0f), 1.0f);
        dx = wx - tt * e1x; dy = wy - tt * e1y;
        dd = fminf(dd, dx * dx + dy * dy);
        wx = px - Cx; wy = py - Cy;
        tt = fminf(fmaxf((wx * e2x + wy * e2y) * i2, 0.0f), 1.0f);
        dx = wx - tt * e2x; dy = wy - tt * e2y;
        dd = fminf(dd, dx * dx + dy * dy);

        if (inside || dd <= 9.00001f) {
            float dist = sqrtf(dd + 1e-12f);     // exact: matches reference
            if (inside || dist <= 3.0f) {
                int slot = atomicAdd(&scr[0], 1);
                if (slot < CAP)
                    key[slot] =
                        ((unsigned long long)__float_as_uint(dist) << 32)
                        | (unsigned)(iy * Ws + ix);
            }
        }
    }
    gsync<GS>(barid);
    const int count = min(scr[0], CAP);
    const float inv = 1.0f / st;

    // ---- two-level histogram select of 64 smallest keys ----
    int pb = 256, sb = 256, r2 = 0;              // count<=64 -> select all
    if (count > 64) {
        for (int i = gl; i < 256; i += GS) hist[i] = 0;
        gsync<GS>(barid);
        for (int e = gl; e < count; e += GS)
            atomicAdd(&hist[(int)((key[e] >> 55) & 0xFF)], 1);
        gsync<GS>(barid);
        if (gl < 32) {
            int bb, cc;
            pivot_warp(hist, 63, lane, bb, cc);
            if (lane == 0) { scr[1] = bb; scr[2] = 64 - cc; }   // pb, need
        }
        gsync<GS>(barid);
        pb = scr[1];
        const int need = scr[2];                 // 1..hist[pb]
        const int hpb  = hist[pb];
        if (hpb > need) {
            gsync<GS>(barid);                    // all read hist before clear
            for (int i = gl; i < 256; i += GS) hist[i] = 0;
            gsync<GS>(barid);
            for (int e = gl; e < count; e += GS) {
                unsigned long long k = key[e];
                if ((int)((k >> 55) & 0xFF) == pb)
                    atomicAdd(&hist[(int)((k >> 47) & 0xFF)], 1);
            }
            gsync<GS>(barid);
            if (gl < 32) {
                int bb, cc;
                pivot_warp(hist, need - 1, lane, bb, cc);
                if (lane == 0) { scr[2] = bb; scr[3] = need - cc; }  // sb, r2
            }
            gsync<GS>(barid);
            sb = scr[2];
            r2 = scr[3];
        }
    }

    float regA = 0.0f, clsA = 0.0f, objA = 0.0f;
    int nv = 0, nn = 0;

    for (int e = gl; e < count; e += GS) {
        const unsigned long long ke = key[e];
        const int eB = (int)((ke >> 55) & 0xFF);
        bool sel;
        if (eB != pb) sel = (eB < pb);
        else {
            const int mB = (int)((ke >> 47) & 0xFF);
            if (mB != sb) sel = (mB < sb);
            else {
                const unsigned long long hi = ke >> 47;
                int rank = 0;
                for (int j = 0; j < count; j++) {
                    unsigned long long kj = key[j];
                    rank += (kj < ke) && ((kj >> 47) == hi);
                }
                sel = (rank < r2);
            }
        }
        if (sel) {
            const int ie = (int)(ke & 0xffffffffu);
            nv++;
            clsA += fast_sp(-cls[(size_t)b * HW + ie]);

            int ix = ie & (Ws - 1), iy = ie >> lg;
            float ax = (ix + 0.5f) * st;
            float ay = (iy + 0.5f) * st;
            float g0x = (Ax - ax) * inv, g0y = (Ay - ay) * inv;
            float g1x = (Bx - ax) * inv, g1y = (By - ay) * inv;
            float g2x = (Cx - ax) * inv, g2y = (Cy - ay) * inv;

            const float* rb = reg + (size_t)b * 6 * HW + ie;
            float p0x = fminf(fmaxf(rb[0],            -64.0f), 64.0f);
            float p0y = fminf(fmaxf(rb[(size_t)HW],   -64.0f), 64.0f);
            float p1x = fminf(fmaxf(rb[(size_t)2*HW], -64.0f), 64.0f);
            float p1y = fminf(fmaxf(rb[(size_t)3*HW], -64.0f), 64.0f);
            float p2x = fminf(fmaxf(rb[(size_t)4*HW], -64.0f), 64.0f);
            float p2y = fminf(fmaxf(rb[(size_t)5*HW], -64.0f), 64.0f);

            float p0 = (p0x - g0x) * (p0x - g0x) + (p0y - g0y) * (p0y - g0y);
            float d11 = sqrtf((p1x-g1x)*(p1x-g1x) + (p1y-g1y)*(p1y-g1y));
            float d12 = sqrtf((p1x-g2x)*(p1x-g2x) + (p1y-g2y)*(p1y-g2y));
            float d21 = sqrtf((p2x-g1x)*(p2x-g1x) + (p2y-g1y)*(p2y-g1y));
            float d22 = sqrtf((p2x-g2x)*(p2x-g2x) + (p2y-g2y)*(p2y-g2y));
            float cd = fminf(d11, d12) + fminf(d21, d22)
                     + fminf(d11, d21) + fminf(d12, d22);
            regA += p0 + cd;

            // objectness correction: first toucher this epoch applies it
            int cell = markBase + ie;
            unsigned old = atomicExch(&g_mark[cell], epoch);
            if (old != epoch) {
                float x = obj[(size_t)b * HW + ie];
                objA += 1.2f * fast_sp(-x) - fast_sp(x);
                nn++;
            }
        }
    }
    acc[0] += (double)regA;
    acc[1] += (double)clsA;
    acc[2] += (double)objA;
    acc[3] += (double)nv;
    acc[4] += (double)nn;
}

__device__ __forceinline__ void dense_chunk(int D, int lane,
                                            const float* __restrict__ obj0,
                                            const float* __restrict__ obj1,
                                            const float* __restrict__ obj2,
                                            double* acc) {
    int base = D * 256;                          // never crosses tensors
    const float* src; int off;
    if (base < 524288)      { src = obj0; off = base; }
    else if (base < 655360) { src = obj1; off = base - 524288; }
    else                    { src = obj2; off = base - 655360; }
    const float4* s4 = (const float4*)(src + off);
    float mx = 0.0f, prod = 1.0f;
#pragma unroll
    for (int k = 0; k < 2; k++) {
        float4 v = s4[lane + k * 32];
        mx += fmaxf(v.x, 0.0f) + fmaxf(v.y, 0.0f)
            + fmaxf(v.z, 0.0f) + fmaxf(v.w, 0.0f);
        prod *= (1.0f + __expf(-fabsf(v.x)))
              * (1.0f + __expf(-fabsf(v.y)))
              * (1.0f + __expf(-fabsf(v.z)))
              * (1.0f + __expf(-fabsf(v.w)));
    }
    acc[2] += (double)(mx + __logf(prod));
}

__global__ void __launch_bounds__(NT, 4)
fused_kernel(const float* __restrict__ reg0, const float* __restrict__ obj0,
             const float* __restrict__ cls0,
             const float* __restrict__ reg1, const float* __restrict__ obj1,
             const float* __restrict__ cls1,
             const float* __restrict__ reg2, const float* __restrict__ obj2,
             const float* __restrict__ cls2,
             const float* __restrict__ gt, float* __restrict__ out) {
    __shared__ SmemU  sm;
    __shared__ double s_w[8][5];

    const int tid  = threadIdx.x;
    const int bid  = blockIdx.x;
    const int wid  = tid >> 5;
    const int lane = tid & 31;
    const unsigned epoch = g_epoch + 1;

    double acc[5];  // 0:reg 1:cls 2:obj 3:pos 4:posnow
#pragma unroll
    for (int c = 0; c < 5; c++) acc[c] = 0.0;

    if (bid < 256) {
        // two 128-thread warpgroups: lvl0 (t<256) and lvl1 (256<=t<512)
        const int grp  = wid >> 2;
        const int gtid = tid & 127;
        pair_task<128, CAP0>(bid * 2 + grp, gtid, 1 + grp,
                             sm.g.key[grp], sm.g.hist[grp], sm.g.scr[grp],
                             reg0, obj0, cls0, reg1, obj1, cls1,
                             reg2, obj2, cls2, gt, epoch, acc);
    } else {
        const int slot = (bid - 256) * 8 + wid;      // 0..2687
        if (slot < 256) {
            // lvl2 warp task + one extra dense chunk
            pair_task<32, CAPW>(512 + slot, lane, 0,
                                sm.w.key[wid], sm.w.hist[wid], sm.w.scr[wid],
                                reg0, obj0, cls0, reg1, obj1, cls1,
                                reg2, obj2, cls2, gt, epoch, acc);
            dense_chunk(2432 + slot, lane, obj0, obj1, obj2, acc);
        } else {
            dense_chunk(slot - 256, lane, obj0, obj1, obj2, acc);
        }
    }

    // ---- block reduce -> 5 global double atomicAdds ----
    __syncthreads();
#pragma unroll
    for (int c = 0; c < 5; c++) {
        double v = acc[c];
#pragma unroll
        for (int o = 16; o > 0; o >>= 1)
            v += __shfl_down_sync(0xffffffffu, v, o);
        if (lane == 0) s_w[wid][c] = v;
    }
    __syncthreads();
    if (tid < 5) {
        double v = 0.0;
#pragma unroll
        for (int w = 0; w < 8; w++) v += s_w[w][tid];
        atomicAdd(&g_tot[tid], v);
    }
    __syncthreads();

    // ---- last block finalizes ----
    if (tid == 0) {
        __threadfence();
        unsigned r = atomicAdd(&g_done, 1);
        if (r == GRID - 1) {
            __threadfence();
            double t0 = *(volatile double*)&g_tot[0];
            double t1 = *(volatile double*)&g_tot[1];
            double t2 = *(volatile double*)&g_tot[2];
            double t3 = *(volatile double*)&g_tot[3];
            double t4 = *(volatile double*)&g_tot[4];
            double pos_eps = fmax(t3, 1.0);
            double neg = fmax((double)TOTAL_CELLS - t4, 1.0);
            double total = t0 / pos_eps + t2 / (pos_eps + neg) + t1 / pos_eps;
            float tt = (float)total;
            out[0] = isfinite(tt) ? tt : 0.0f;
            // reset state for next (graph-replayed) launch
            g_tot[0] = 0.0; g_tot[1] = 0.0; g_tot[2] = 0.0;
            g_tot[3] = 0.0; g_tot[4] = 0.0;
            g_epoch = epoch;
            __threadfence();
            g_done = 0;
        }
    }
}

extern "C" void kernel_launch(void* const* d_in, const int* in_sizes, int n_in,
                              void* d_out, int out_size) {
    (void)in_sizes; (void)n_in; (void)out_size;
    fused_kernel<<<GRID, NT>>>(
        (const float*)d_in[0], (const float*)d_in[1], (const float*)d_in[2],
        (const float*)d_in[3], (const float*)d_in[4], (const float*)d_in[5],
        (const float*)d_in[6], (const float*)d_in[7], (const float*)d_in[8],
        (const float*)d_in[9], (float*)d_out);
}